// round 2
// baseline (speedup 1.0000x reference)
#include <cuda_runtime.h>
#include <cuda_bf16.h>
#include <cstdint>
#include <math.h>

// ---------------------------------------------------------------------------
// Problem constants
// ---------------------------------------------------------------------------
#define NROWS     8192     // rows in z_i (and z_j)
#define DIM       512      // feature dim
#define BROWS     16384    // combined B rows (zi ++ zj)

#define BM        128      // CTA tile M
#define BN        256      // CTA tile N
#define BK        64       // K chunk (bf16 elems) = 128 bytes/row
#define CHUNKS    (DIM / BK)   // 8
#define STAGES    3

#define CHUNK_A_BYTES (BM * BK * 2)          // 16384
#define CHUNK_B_BYTES (BN * BK * 2)          // 32768
#define STAGE_BYTES   (CHUNK_A_BYTES + CHUNK_B_BYTES)  // 49152
#define SMEM_TOTAL    (STAGES * STAGE_BYTES)           // 147456

// ---------------------------------------------------------------------------
// Global scratch (allocation-free rules: __device__ globals)
// ---------------------------------------------------------------------------
__device__ __nv_bfloat16 g_z[(size_t)BROWS * DIM];   // 16 MB: rows 0..8191 zi, 8192.. zj
__device__ double g_pos;
__device__ double g_neg;

// ---------------------------------------------------------------------------
// PTX helpers — only sm_80-era features (PTX target is plain sm_103; no tcgen05)
// ---------------------------------------------------------------------------
__device__ __forceinline__ uint32_t smem_to_u32(const void* p) {
    uint32_t a;
    asm("{ .reg .u64 t; cvta.to.shared.u64 t, %1; cvt.u32.u64 %0, t; }" : "=r"(a) : "l"(p));
    return a;
}

#define SWZ(off) ((off) ^ (((off) >> 3) & 0x70u))   // SW128 swizzle for 128B rows

__device__ __forceinline__ void cp_async16(uint32_t dst_smem, const void* src) {
    asm volatile("cp.async.cg.shared.global [%0], [%1], 16;" :: "r"(dst_smem), "l"(src));
}
#define CP_ASYNC_COMMIT() asm volatile("cp.async.commit_group;" ::: "memory")
#define CP_ASYNC_WAIT_1() asm volatile("cp.async.wait_group 1;" ::: "memory")

__device__ __forceinline__ void ldmatrix_x4(uint32_t* r, uint32_t addr) {
    asm volatile("ldmatrix.sync.aligned.m8n8.x4.shared.b16 {%0,%1,%2,%3}, [%4];"
                 : "=r"(r[0]), "=r"(r[1]), "=r"(r[2]), "=r"(r[3]) : "r"(addr));
}

// D = A * B^T accumulate: mma.sync m16n8k16, bf16 in, fp32 accum
__device__ __forceinline__ void mma_bf16(float* c, const uint32_t* a, uint32_t b0, uint32_t b1) {
    asm volatile(
        "mma.sync.aligned.m16n8k16.row.col.f32.bf16.bf16.f32 "
        "{%0,%1,%2,%3}, {%4,%5,%6,%7}, {%8,%9}, {%0,%1,%2,%3};"
        : "+f"(c[0]), "+f"(c[1]), "+f"(c[2]), "+f"(c[3])
        : "r"(a[0]), "r"(a[1]), "r"(a[2]), "r"(a[3]), "r"(b0), "r"(b1));
}

// ---------------------------------------------------------------------------
// Kernel 1: L2-normalize rows of z_i and z_j into bf16 g_z; reset accumulators
// ---------------------------------------------------------------------------
__global__ __launch_bounds__(128) void norm_kernel(const float* __restrict__ zi,
                                                   const float* __restrict__ zj) {
    int row = blockIdx.x;                 // 0..16383
    int tid = threadIdx.x;                // 128 threads, 4 floats each
    if (row == 0 && tid == 0) { g_pos = 0.0; g_neg = 0.0; }

    const float* src = (row < NROWS) ? (zi + (size_t)row * DIM)
                                     : (zj + (size_t)(row - NROWS) * DIM);
    float4 v = reinterpret_cast<const float4*>(src)[tid];
    float ss = v.x * v.x + v.y * v.y + v.z * v.z + v.w * v.w;
    #pragma unroll
    for (int off = 16; off > 0; off >>= 1)
        ss += __shfl_xor_sync(0xFFFFFFFFu, ss, off);

    __shared__ float s4[4];
    int wid = tid >> 5;
    if ((tid & 31) == 0) s4[wid] = ss;
    __syncthreads();
    float tot = s4[0] + s4[1] + s4[2] + s4[3];
    float scale = 1.0f / fmaxf(sqrtf(tot), 1e-12f);

    __nv_bfloat162* dst = reinterpret_cast<__nv_bfloat162*>(g_z + (size_t)row * DIM + tid * 4);
    dst[0] = __floats2bfloat162_rn(v.x * scale, v.y * scale);
    dst[1] = __floats2bfloat162_rn(v.z * scale, v.w * scale);
}

// ---------------------------------------------------------------------------
// Kernel 2: fused GEMM (mma.sync bf16) + exp-sum epilogue over registers.
// Grid (64, 64): tile (tm, tn) covers A rows [tm*128, +128), B rows [tn*256, +256).
// 8 warps: warpM = wid&1 (x64), warpN = wid>>1 (x64). Warp tile 64x64.
// ---------------------------------------------------------------------------
__global__ __launch_bounds__(256) void gemm_kernel() {
    extern __shared__ __align__(1024) char smem[];
    const uint32_t sb = smem_to_u32(smem);
    const int tid   = threadIdx.x;
    const int wid   = tid >> 5;
    const int lane  = tid & 31;
    const int warpM = (wid & 1) * 64;
    const int warpN = (wid >> 1) * 64;

    const char* gzA = reinterpret_cast<const char*>(g_z) + (size_t)blockIdx.x * BM * (DIM * 2);
    const char* gzB = reinterpret_cast<const char*>(g_z) + (size_t)blockIdx.y * BN * (DIM * 2);

    float acc[4][8][4];       // [mBlock16][nBlock8][frag] = 128 regs
    #pragma unroll
    for (int i = 0; i < 4; i++)
        #pragma unroll
        for (int j = 0; j < 8; j++)
            #pragma unroll
            for (int k = 0; k < 4; k++) acc[i][j][k] = 0.0f;

    // -------- chunk loader: 12 x cp.async(16B) per thread --------
    auto load_chunk = [&](int c, int st) {
        uint32_t stA = sb + st * STAGE_BYTES;
        uint32_t stB = stA + CHUNK_A_BYTES;
        const char* srcA = gzA + c * (BK * 2);   // 128 bytes of K
        const char* srcB = gzB + c * (BK * 2);
        #pragma unroll
        for (int i = 0; i < 4; i++) {            // A: 1024 16B units
            int u = tid + i * 256;
            int r = u >> 3, c16 = u & 7;
            uint32_t off = (uint32_t)(r * 128 + c16 * 16);
            cp_async16(stA + SWZ(off), srcA + (size_t)r * (DIM * 2) + c16 * 16);
        }
        #pragma unroll
        for (int i = 0; i < 8; i++) {            // B: 2048 16B units
            int u = tid + i * 256;
            int r = u >> 3, c16 = u & 7;
            uint32_t off = (uint32_t)(r * 128 + c16 * 16);
            cp_async16(stB + SWZ(off), srcB + (size_t)r * (DIM * 2) + c16 * 16);
        }
        CP_ASYNC_COMMIT();
    };

    // -------- chunk compute: 4 ksteps x (8 ldmatrix.x4 + 32 mma) --------
    const int ldRow  = lane & 15;          // row within 16-row ldmatrix block
    const int ldColB = (lane >> 4) << 4;   // 0 or 16 bytes

    auto compute_chunk = [&](int st) {
        uint32_t stA = sb + st * STAGE_BYTES;
        uint32_t stB = stA + CHUNK_A_BYTES;
        #pragma unroll
        for (int ks = 0; ks < 4; ks++) {
            uint32_t a[4][4], b[4][4];
            #pragma unroll
            for (int mb = 0; mb < 4; mb++) {
                uint32_t off = (uint32_t)((warpM + mb * 16 + ldRow) * 128 + ks * 32 + ldColB);
                ldmatrix_x4(a[mb], stA + SWZ(off));
            }
            #pragma unroll
            for (int nb = 0; nb < 4; nb++) {
                uint32_t off = (uint32_t)((warpN + nb * 16 + ldRow) * 128 + ks * 32 + ldColB);
                ldmatrix_x4(b[nb], stB + SWZ(off));
            }
            #pragma unroll
            for (int mb = 0; mb < 4; mb++)
                #pragma unroll
                for (int nb = 0; nb < 4; nb++) {
                    mma_bf16(acc[mb][nb * 2 + 0], a[mb], b[nb][0], b[nb][2]);
                    mma_bf16(acc[mb][nb * 2 + 1], a[mb], b[nb][1], b[nb][3]);
                }
        }
    };

    // -------- 3-stage pipeline --------
    load_chunk(0, 0);
    load_chunk(1, 1);

    #pragma unroll 1
    for (int c = 0; c < CHUNKS; c++) {
        CP_ASYNC_WAIT_1();      // chunk c resident (<=1 group pending)
        __syncthreads();        // all threads' loads of chunk c visible; prev compute done
        int nc = c + 2;
        if (nc < CHUNKS) load_chunk(nc, nc % STAGES);  // slot held chunk c-1: free
        compute_chunk(c % STAGES);
    }

    // -------- epilogue: sum exp(10 * acc) --------
    float lsum = 0.0f;
    #pragma unroll
    for (int i = 0; i < 4; i++)
        #pragma unroll
        for (int j = 0; j < 8; j++)
            #pragma unroll
            for (int k = 0; k < 4; k++)
                lsum += __expf(10.0f * acc[i][j][k]);

    #pragma unroll
    for (int off = 16; off > 0; off >>= 1)
        lsum += __shfl_xor_sync(0xFFFFFFFFu, lsum, off);

    __shared__ double wsum[8];
    if (lane == 0) wsum[wid] = (double)lsum;
    __syncthreads();
    if (tid == 0) {
        double t = 0.0;
        #pragma unroll
        for (int w = 0; w < 8; w++) t += wsum[w];
        // tiles never straddle the zi/zj boundary: 8192 / 256 = 32
        atomicAdd((blockIdx.y < (NROWS / BN)) ? &g_pos : &g_neg, t);
    }
}

// ---------------------------------------------------------------------------
// Kernel 3: loss = -log(pos / (neg + pos))
// ---------------------------------------------------------------------------
__global__ void finish_kernel(float* out) {
    double p = g_pos, n = g_neg;
    out[0] = (float)(-log(p / (n + p)));
}

// ---------------------------------------------------------------------------
extern "C" void kernel_launch(void* const* d_in, const int* in_sizes, int n_in,
                              void* d_out, int out_size) {
    const float* zi = (const float*)d_in[0];
    const float* zj = (const float*)d_in[1];
    float* out = (float*)d_out;

    cudaFuncSetAttribute(gemm_kernel, cudaFuncAttributeMaxDynamicSharedMemorySize, SMEM_TOTAL);

    norm_kernel<<<BROWS, 128>>>(zi, zj);
    dim3 grid(NROWS / BM, BROWS / BN);   // (64, 64)
    gemm_kernel<<<grid, 256, SMEM_TOTAL>>>();
    finish_kernel<<<1, 1>>>(out);
}

// round 3
// speedup vs baseline: 1.2654x; 1.2654x over previous
#include <cuda_runtime.h>
#include <cuda_bf16.h>
#include <cstdint>
#include <math.h>

// ---------------------------------------------------------------------------
// Problem constants
// ---------------------------------------------------------------------------
#define NROWS     8192     // rows in z_i (and z_j)
#define DIM       512      // feature dim
#define BROWS     16384    // combined B rows (zi ++ zj)

#define BM        128      // CTA tile M
#define BN        256      // CTA tile N
#define BK        64       // K chunk (bf16 elems) = 128 bytes/row
#define CHUNKS    (DIM / BK)   // 8
#define STAGES    3

#define CHUNK_A_BYTES (BM * BK * 2)          // 16384
#define CHUNK_B_BYTES (BN * BK * 2)          // 32768
#define STAGE_BYTES   (CHUNK_A_BYTES + CHUNK_B_BYTES)  // 49152
#define SMEM_TOTAL    (STAGES * STAGE_BYTES)           // 147456

#define NEG_TILES 2048     // 64 x 32 full tiles for zi x zj
#define POS_TILES 1056     // upper-triangular 128-block coverage of zi x zi
#define TOTAL_TILES (NEG_TILES + POS_TILES)  // 3104

// ---------------------------------------------------------------------------
// Global scratch (allocation-free rules: __device__ globals)
// ---------------------------------------------------------------------------
__device__ __nv_bfloat16 g_z[(size_t)BROWS * DIM];   // 16 MB: rows 0..8191 zi, 8192.. zj
__device__ double g_pos;
__device__ double g_neg;

// ---------------------------------------------------------------------------
// PTX helpers — only sm_80-era features (PTX target is plain sm_103; no tcgen05)
// ---------------------------------------------------------------------------
__device__ __forceinline__ uint32_t smem_to_u32(const void* p) {
    uint32_t a;
    asm("{ .reg .u64 t; cvta.to.shared.u64 t, %1; cvt.u32.u64 %0, t; }" : "=r"(a) : "l"(p));
    return a;
}

#define SWZ(off) ((off) ^ (((off) >> 3) & 0x70u))   // SW128 swizzle for 128B rows

__device__ __forceinline__ void cp_async16(uint32_t dst_smem, const void* src) {
    asm volatile("cp.async.cg.shared.global [%0], [%1], 16;" :: "r"(dst_smem), "l"(src));
}
#define CP_ASYNC_COMMIT() asm volatile("cp.async.commit_group;" ::: "memory")
#define CP_ASYNC_WAIT_1() asm volatile("cp.async.wait_group 1;" ::: "memory")

__device__ __forceinline__ void ldmatrix_x4(uint32_t* r, uint32_t addr) {
    asm volatile("ldmatrix.sync.aligned.m8n8.x4.shared.b16 {%0,%1,%2,%3}, [%4];"
                 : "=r"(r[0]), "=r"(r[1]), "=r"(r[2]), "=r"(r[3]) : "r"(addr));
}

// D = A * B^T accumulate: mma.sync m16n8k16, bf16 in, fp32 accum
__device__ __forceinline__ void mma_bf16(float* c, const uint32_t* a, uint32_t b0, uint32_t b1) {
    asm volatile(
        "mma.sync.aligned.m16n8k16.row.col.f32.bf16.bf16.f32 "
        "{%0,%1,%2,%3}, {%4,%5,%6,%7}, {%8,%9}, {%0,%1,%2,%3};"
        : "+f"(c[0]), "+f"(c[1]), "+f"(c[2]), "+f"(c[3])
        : "r"(a[0]), "r"(a[1]), "r"(a[2]), "r"(a[3]), "r"(b0), "r"(b1));
}

// ---------------------------------------------------------------------------
// Kernel 1: L2-normalize rows into bf16 g_z. One warp per row, 4 independent
// float4 loads per lane (MLP=4). Also resets accumulators.
// ---------------------------------------------------------------------------
__global__ __launch_bounds__(256) void norm_kernel(const float* __restrict__ zi,
                                                   const float* __restrict__ zj) {
    const int tid  = threadIdx.x;
    const int lane = tid & 31;
    const int row  = blockIdx.x * 8 + (tid >> 5);   // 2048 blocks x 8 warps
    if (blockIdx.x == 0 && tid == 0) { g_pos = 0.0; g_neg = 0.0; }

    const float* src = (row < NROWS) ? (zi + (size_t)row * DIM)
                                     : (zj + (size_t)(row - NROWS) * DIM);
    const float4* s4 = reinterpret_cast<const float4*>(src);
    float4 v[4];
    #pragma unroll
    for (int k = 0; k < 4; k++) v[k] = s4[lane + 32 * k];

    float ss = 0.0f;
    #pragma unroll
    for (int k = 0; k < 4; k++)
        ss += v[k].x * v[k].x + v[k].y * v[k].y + v[k].z * v[k].z + v[k].w * v[k].w;
    #pragma unroll
    for (int off = 16; off > 0; off >>= 1)
        ss += __shfl_xor_sync(0xFFFFFFFFu, ss, off);

    float scale = 1.0f / fmaxf(sqrtf(ss), 1e-12f);

    __nv_bfloat162* dst = reinterpret_cast<__nv_bfloat162*>(g_z + (size_t)row * DIM);
    #pragma unroll
    for (int k = 0; k < 4; k++) {
        int e = lane + 32 * k;
        dst[e * 2 + 0] = __floats2bfloat162_rn(v[k].x * scale, v[k].y * scale);
        dst[e * 2 + 1] = __floats2bfloat162_rn(v[k].z * scale, v[k].w * scale);
    }
}

// ---------------------------------------------------------------------------
// Kernel 2: fused GEMM (mma.sync bf16) + weighted exp-sum epilogue.
// 1-D grid of 3104 tiles:
//   idx < 2048 : neg tile, tm = idx&63, B rows = NROWS + (idx>>6)*256, w=1
//   idx >= 2048: pos tile p: tn = tri-decode(p), tm = i; upper-block coverage
//                with per-128-col-half weights (2 / 1-diag / 0) for symmetry.
// 8 warps: warpM=(wid&1)*64, warpN=(wid>>1)*64; each warp's accumulator sits
// entirely in one column half -> weight is per-warp scalar.
// ---------------------------------------------------------------------------
__global__ __launch_bounds__(256) void gemm_kernel() {
    extern __shared__ __align__(1024) char smem[];
    const uint32_t sb = smem_to_u32(smem);
    const int tid   = threadIdx.x;
    const int wid   = tid >> 5;
    const int lane  = tid & 31;
    const int warpM = (wid & 1) * 64;
    const int warpN = (wid >> 1) * 64;

    // ---- tile decode ----
    int tm, rowB;
    float w0, w1;
    bool is_pos;
    {
        int idx = blockIdx.x;
        if (idx < NEG_TILES) {
            tm   = idx & 63;
            rowB = NROWS + (idx >> 6) * BN;
            w0 = w1 = 1.0f;
            is_pos = false;
        } else {
            int p = idx - NEG_TILES;
            int t = (int)((sqrtf((float)(4 * p + 1)) - 1.0f) * 0.5f);
            while ((t + 1) * (t + 2) <= p) t++;
            while (t * (t + 1) > p) t--;
            int i = p - t * (t + 1);       // 0 .. 2t+1
            tm   = i;
            rowB = t * BN;
            if (i < 2 * t)       { w0 = 2.0f; w1 = 2.0f; }
            else if (i == 2 * t) { w0 = 1.0f; w1 = 2.0f; }
            else                 { w0 = 0.0f; w1 = 1.0f; }
            is_pos = true;
        }
    }
    const float wwarp = (wid >= 4) ? w1 : w0;

    const char* gzA = reinterpret_cast<const char*>(g_z) + (size_t)tm * BM * (DIM * 2);
    const char* gzB = reinterpret_cast<const char*>(g_z) + (size_t)rowB * (DIM * 2);

    float acc[4][8][4];       // [mBlock16][nBlock8][frag] = 128 regs
    #pragma unroll
    for (int i = 0; i < 4; i++)
        #pragma unroll
        for (int j = 0; j < 8; j++)
            #pragma unroll
            for (int k = 0; k < 4; k++) acc[i][j][k] = 0.0f;

    // -------- chunk loader: 12 x cp.async(16B) per thread --------
    auto load_chunk = [&](int c, int st) {
        uint32_t stA = sb + st * STAGE_BYTES;
        uint32_t stB = stA + CHUNK_A_BYTES;
        const char* srcA = gzA + c * (BK * 2);   // 128 bytes of K
        const char* srcB = gzB + c * (BK * 2);
        #pragma unroll
        for (int i = 0; i < 4; i++) {            // A: 1024 16B units
            int u = tid + i * 256;
            int r = u >> 3, c16 = u & 7;
            uint32_t off = (uint32_t)(r * 128 + c16 * 16);
            cp_async16(stA + SWZ(off), srcA + (size_t)r * (DIM * 2) + c16 * 16);
        }
        #pragma unroll
        for (int i = 0; i < 8; i++) {            // B: 2048 16B units
            int u = tid + i * 256;
            int r = u >> 3, c16 = u & 7;
            uint32_t off = (uint32_t)(r * 128 + c16 * 16);
            cp_async16(stB + SWZ(off), srcB + (size_t)r * (DIM * 2) + c16 * 16);
        }
        CP_ASYNC_COMMIT();
    };

    // -------- chunk compute: 4 ksteps x (8 ldmatrix.x4 + 32 mma) --------
    const int ldRow  = lane & 15;          // row within 16-row ldmatrix block
    const int ldColB = (lane >> 4) << 4;   // 0 or 16 bytes

    auto compute_chunk = [&](int st) {
        uint32_t stA = sb + st * STAGE_BYTES;
        uint32_t stB = stA + CHUNK_A_BYTES;
        #pragma unroll
        for (int ks = 0; ks < 4; ks++) {
            uint32_t a[4][4], b[4][4];
            #pragma unroll
            for (int mb = 0; mb < 4; mb++) {
                uint32_t off = (uint32_t)((warpM + mb * 16 + ldRow) * 128 + ks * 32 + ldColB);
                ldmatrix_x4(a[mb], stA + SWZ(off));
            }
            #pragma unroll
            for (int nb = 0; nb < 4; nb++) {
                uint32_t off = (uint32_t)((warpN + nb * 16 + ldRow) * 128 + ks * 32 + ldColB);
                ldmatrix_x4(b[nb], stB + SWZ(off));
            }
            #pragma unroll
            for (int mb = 0; mb < 4; mb++)
                #pragma unroll
                for (int nb = 0; nb < 4; nb++) {
                    mma_bf16(acc[mb][nb * 2 + 0], a[mb], b[nb][0], b[nb][2]);
                    mma_bf16(acc[mb][nb * 2 + 1], a[mb], b[nb][1], b[nb][3]);
                }
        }
    };

    // -------- 3-stage pipeline --------
    load_chunk(0, 0);
    load_chunk(1, 1);

    #pragma unroll 1
    for (int c = 0; c < CHUNKS; c++) {
        CP_ASYNC_WAIT_1();      // chunk c resident (<=1 group pending)
        __syncthreads();        // all threads' loads of chunk c visible; prev compute done
        int nc = c + 2;
        if (nc < CHUNKS) load_chunk(nc, nc % STAGES);  // slot held chunk c-1: free
        compute_chunk(c % STAGES);
    }

    // -------- epilogue: weighted sum of exp(10 * acc) --------
    float lsum = 0.0f;
    if (wwarp != 0.0f) {
        #pragma unroll
        for (int i = 0; i < 4; i++)
            #pragma unroll
            for (int j = 0; j < 8; j++)
                #pragma unroll
                for (int k = 0; k < 4; k++)
                    lsum += __expf(10.0f * acc[i][j][k]);
        lsum *= wwarp;
    }

    #pragma unroll
    for (int off = 16; off > 0; off >>= 1)
        lsum += __shfl_xor_sync(0xFFFFFFFFu, lsum, off);

    __shared__ double wsum[8];
    if (lane == 0) wsum[wid] = (double)lsum;
    __syncthreads();
    if (tid == 0) {
        double t = 0.0;
        #pragma unroll
        for (int w = 0; w < 8; w++) t += wsum[w];
        atomicAdd(is_pos ? &g_pos : &g_neg, t);
    }
}

// ---------------------------------------------------------------------------
// Kernel 3: loss = -log(pos / (neg + pos))
// ---------------------------------------------------------------------------
__global__ void finish_kernel(float* out) {
    double p = g_pos, n = g_neg;
    out[0] = (float)(-log(p / (n + p)));
}

// ---------------------------------------------------------------------------
extern "C" void kernel_launch(void* const* d_in, const int* in_sizes, int n_in,
                              void* d_out, int out_size) {
    const float* zi = (const float*)d_in[0];
    const float* zj = (const float*)d_in[1];
    float* out = (float*)d_out;

    cudaFuncSetAttribute(gemm_kernel, cudaFuncAttributeMaxDynamicSharedMemorySize, SMEM_TOTAL);

    norm_kernel<<<BROWS / 8, 256>>>(zi, zj);
    gemm_kernel<<<TOTAL_TILES, 256, SMEM_TOTAL>>>();
    finish_kernel<<<1, 1>>>(out);
}

// round 4
// speedup vs baseline: 1.5109x; 1.1940x over previous
#include <cuda_runtime.h>
#include <cuda_bf16.h>
#include <cstdint>
#include <math.h>

// ---------------------------------------------------------------------------
// Problem constants
// ---------------------------------------------------------------------------
#define NROWS     8192     // rows in z_i (and z_j)
#define DIM       512      // feature dim
#define BROWS     16384    // combined B rows (zi ++ zj)

#define BM        128      // CTA tile M
#define BN        128      // CTA tile N
#define BK        64       // K chunk (bf16 elems) = 128 bytes/row
#define CHUNKS    (DIM / BK)   // 8
#define STAGES    3

#define CHUNK_A_BYTES (BM * BK * 2)          // 16384
#define CHUNK_B_BYTES (BN * BK * 2)          // 16384
#define STAGE_BYTES   (CHUNK_A_BYTES + CHUNK_B_BYTES)  // 32768
#define SMEM_TOTAL    (STAGES * STAGE_BYTES)           // 98304 -> 2 CTAs/SM

#define NEG_TILES 4096     // 64 x 64 full tiles for zi x zj
#define POS_TILES 2080     // upper triangle incl diag of 64x64 blocks (zi x zi)
#define TOTAL_TILES (NEG_TILES + POS_TILES)  // 6176

// ---------------------------------------------------------------------------
// Global scratch (allocation-free rules: __device__ globals)
// ---------------------------------------------------------------------------
__device__ __nv_bfloat16 g_z[(size_t)BROWS * DIM];   // 16 MB: rows 0..8191 zi, 8192.. zj
__device__ double g_pos;
__device__ double g_neg;

// ---------------------------------------------------------------------------
// PTX helpers — only sm_80-era features (PTX target is plain sm_103; no tcgen05)
// ---------------------------------------------------------------------------
__device__ __forceinline__ uint32_t smem_to_u32(const void* p) {
    uint32_t a;
    asm("{ .reg .u64 t; cvta.to.shared.u64 t, %1; cvt.u32.u64 %0, t; }" : "=r"(a) : "l"(p));
    return a;
}

#define SWZ(off) ((off) ^ (((off) >> 3) & 0x70u))   // SW128 swizzle for 128B rows

__device__ __forceinline__ void cp_async16(uint32_t dst_smem, const void* src) {
    asm volatile("cp.async.cg.shared.global [%0], [%1], 16;" :: "r"(dst_smem), "l"(src));
}
#define CP_ASYNC_COMMIT() asm volatile("cp.async.commit_group;" ::: "memory")
#define CP_ASYNC_WAIT_1() asm volatile("cp.async.wait_group 1;" ::: "memory")

__device__ __forceinline__ void ldmatrix_x4(uint32_t* r, uint32_t addr) {
    asm volatile("ldmatrix.sync.aligned.m8n8.x4.shared.b16 {%0,%1,%2,%3}, [%4];"
                 : "=r"(r[0]), "=r"(r[1]), "=r"(r[2]), "=r"(r[3]) : "r"(addr));
}

// D = A * B^T accumulate: mma.sync m16n8k16, bf16 in, fp32 accum
__device__ __forceinline__ void mma_bf16(float* c, const uint32_t* a, uint32_t b0, uint32_t b1) {
    asm volatile(
        "mma.sync.aligned.m16n8k16.row.col.f32.bf16.bf16.f32 "
        "{%0,%1,%2,%3}, {%4,%5,%6,%7}, {%8,%9}, {%0,%1,%2,%3};"
        : "+f"(c[0]), "+f"(c[1]), "+f"(c[2]), "+f"(c[3])
        : "r"(a[0]), "r"(a[1]), "r"(a[2]), "r"(a[3]), "r"(b0), "r"(b1));
}

// ---------------------------------------------------------------------------
// Kernel 1: L2-normalize rows into bf16 g_z. One warp per row, 4 independent
// float4 loads per lane (MLP=4). Also resets accumulators.
// ---------------------------------------------------------------------------
__global__ __launch_bounds__(256) void norm_kernel(const float* __restrict__ zi,
                                                   const float* __restrict__ zj) {
    const int tid  = threadIdx.x;
    const int lane = tid & 31;
    const int row  = blockIdx.x * 8 + (tid >> 5);   // 2048 blocks x 8 warps
    if (blockIdx.x == 0 && tid == 0) { g_pos = 0.0; g_neg = 0.0; }

    const float* src = (row < NROWS) ? (zi + (size_t)row * DIM)
                                     : (zj + (size_t)(row - NROWS) * DIM);
    const float4* s4 = reinterpret_cast<const float4*>(src);
    float4 v[4];
    #pragma unroll
    for (int k = 0; k < 4; k++) v[k] = s4[lane + 32 * k];

    float ss = 0.0f;
    #pragma unroll
    for (int k = 0; k < 4; k++)
        ss += v[k].x * v[k].x + v[k].y * v[k].y + v[k].z * v[k].z + v[k].w * v[k].w;
    #pragma unroll
    for (int off = 16; off > 0; off >>= 1)
        ss += __shfl_xor_sync(0xFFFFFFFFu, ss, off);

    float scale = 1.0f / fmaxf(sqrtf(ss), 1e-12f);

    __nv_bfloat162* dst = reinterpret_cast<__nv_bfloat162*>(g_z + (size_t)row * DIM);
    #pragma unroll
    for (int k = 0; k < 4; k++) {
        int e = lane + 32 * k;
        dst[e * 2 + 0] = __floats2bfloat162_rn(v[k].x * scale, v[k].y * scale);
        dst[e * 2 + 1] = __floats2bfloat162_rn(v[k].z * scale, v[k].w * scale);
    }
}

// ---------------------------------------------------------------------------
// Kernel 2: fused GEMM (mma.sync bf16) + weighted exp-sum epilogue.
// 128x128 tiles, 4 warps (64x64 warp tile), 2 CTAs/SM (96KB smem each) so
// one CTA's HMMAs cover the other's barrier/prologue bubbles.
// Tile decode (1-D grid, 6176 tiles):
//   idx < 4096 : neg tile: tm = idx&63, B rows = NROWS + (idx>>6)*128, w=1
//   idx >= 4096: pos tile p -> lower-tri (t,i), i<=t: tm=i, B rows = t*128,
//                w = (i==t) ? 1 : 2   (symmetry of zi x zi^T)
// ---------------------------------------------------------------------------
__global__ __launch_bounds__(128, 2) void gemm_kernel() {
    extern __shared__ __align__(1024) char smem[];
    const uint32_t sb = smem_to_u32(smem);
    const int tid   = threadIdx.x;
    const int wid   = tid >> 5;
    const int lane  = tid & 31;
    const int warpM = (wid & 1) * 64;
    const int warpN = (wid >> 1) * 64;

    // ---- tile decode ----
    int tm, rowB;
    float wtile;
    bool is_pos;
    {
        int idx = blockIdx.x;
        if (idx < NEG_TILES) {
            tm    = idx & 63;
            rowB  = NROWS + (idx >> 6) * BN;
            wtile = 1.0f;
            is_pos = false;
        } else {
            int p = idx - NEG_TILES;                    // 0 .. 2079
            int t = (int)((sqrtf((float)(8 * p + 1)) - 1.0f) * 0.5f);
            while ((t + 1) * (t + 2) / 2 <= p) t++;
            while (t * (t + 1) / 2 > p) t--;
            int i = p - t * (t + 1) / 2;                // 0 .. t
            tm    = i;
            rowB  = t * BN;
            wtile = (i == t) ? 1.0f : 2.0f;
            is_pos = true;
        }
    }

    const char* gzA = reinterpret_cast<const char*>(g_z) + (size_t)tm * BM * (DIM * 2);
    const char* gzB = reinterpret_cast<const char*>(g_z) + (size_t)rowB * (DIM * 2);

    float acc[4][8][4];       // [mBlock16][nBlock8][frag] = 128 regs
    #pragma unroll
    for (int i = 0; i < 4; i++)
        #pragma unroll
        for (int j = 0; j < 8; j++)
            #pragma unroll
            for (int k = 0; k < 4; k++) acc[i][j][k] = 0.0f;

    // -------- chunk loader: 16 x cp.async(16B) per thread (A 8 + B 8) --------
    auto load_chunk = [&](int c, int st) {
        uint32_t stA = sb + st * STAGE_BYTES;
        uint32_t stB = stA + CHUNK_A_BYTES;
        const char* srcA = gzA + c * (BK * 2);   // 128 bytes of K
        const char* srcB = gzB + c * (BK * 2);
        #pragma unroll
        for (int i = 0; i < 8; i++) {            // A: 1024 16B units / 128 thr
            int u = tid + i * 128;
            int r = u >> 3, c16 = u & 7;
            uint32_t off = (uint32_t)(r * 128 + c16 * 16);
            cp_async16(stA + SWZ(off), srcA + (size_t)r * (DIM * 2) + c16 * 16);
        }
        #pragma unroll
        for (int i = 0; i < 8; i++) {            // B: 1024 16B units / 128 thr
            int u = tid + i * 128;
            int r = u >> 3, c16 = u & 7;
            uint32_t off = (uint32_t)(r * 128 + c16 * 16);
            cp_async16(stB + SWZ(off), srcB + (size_t)r * (DIM * 2) + c16 * 16);
        }
        CP_ASYNC_COMMIT();
    };

    // -------- chunk compute: 4 ksteps x (8 ldmatrix.x4 + 32 mma) --------
    const int ldRow  = lane & 15;          // row within 16-row ldmatrix block
    const int ldColB = (lane >> 4) << 4;   // 0 or 16 bytes

    auto compute_chunk = [&](int st) {
        uint32_t stA = sb + st * STAGE_BYTES;
        uint32_t stB = stA + CHUNK_A_BYTES;
        #pragma unroll
        for (int ks = 0; ks < 4; ks++) {
            uint32_t a[4][4], b[4][4];
            #pragma unroll
            for (int mb = 0; mb < 4; mb++) {
                uint32_t off = (uint32_t)((warpM + mb * 16 + ldRow) * 128 + ks * 32 + ldColB);
                ldmatrix_x4(a[mb], stA + SWZ(off));
            }
            #pragma unroll
            for (int nb = 0; nb < 4; nb++) {
                uint32_t off = (uint32_t)((warpN + nb * 16 + ldRow) * 128 + ks * 32 + ldColB);
                ldmatrix_x4(b[nb], stB + SWZ(off));
            }
            #pragma unroll
            for (int mb = 0; mb < 4; mb++)
                #pragma unroll
                for (int nb = 0; nb < 4; nb++) {
                    mma_bf16(acc[mb][nb * 2 + 0], a[mb], b[nb][0], b[nb][2]);
                    mma_bf16(acc[mb][nb * 2 + 1], a[mb], b[nb][1], b[nb][3]);
                }
        }
    };

    // -------- 3-stage pipeline --------
    load_chunk(0, 0);
    load_chunk(1, 1);

    #pragma unroll 1
    for (int c = 0; c < CHUNKS; c++) {
        CP_ASYNC_WAIT_1();      // chunk c resident (<=1 group pending)
        __syncthreads();        // all threads' loads of chunk c visible; prev compute done
        int nc = c + 2;
        if (nc < CHUNKS) load_chunk(nc, nc % STAGES);  // slot held chunk c-1: free
        compute_chunk(c % STAGES);
    }

    // -------- epilogue: weighted sum of exp(10 * acc) --------
    float lsum = 0.0f;
    #pragma unroll
    for (int i = 0; i < 4; i++)
        #pragma unroll
        for (int j = 0; j < 8; j++)
            #pragma unroll
            for (int k = 0; k < 4; k++)
                lsum += __expf(10.0f * acc[i][j][k]);
    lsum *= wtile;

    #pragma unroll
    for (int off = 16; off > 0; off >>= 1)
        lsum += __shfl_xor_sync(0xFFFFFFFFu, lsum, off);

    __shared__ double wsum[4];
    if (lane == 0) wsum[wid] = (double)lsum;
    __syncthreads();
    if (tid == 0) {
        double t = wsum[0] + wsum[1] + wsum[2] + wsum[3];
        atomicAdd(is_pos ? &g_pos : &g_neg, t);
    }
}

// ---------------------------------------------------------------------------
// Kernel 3: loss = -log(pos / (neg + pos))
// ---------------------------------------------------------------------------
__global__ void finish_kernel(float* out) {
    double p = g_pos, n = g_neg;
    out[0] = (float)(-log(p / (n + p)));
}

// ---------------------------------------------------------------------------
extern "C" void kernel_launch(void* const* d_in, const int* in_sizes, int n_in,
                              void* d_out, int out_size) {
    const float* zi = (const float*)d_in[0];
    const float* zj = (const float*)d_in[1];
    float* out = (float*)d_out;

    cudaFuncSetAttribute(gemm_kernel, cudaFuncAttributeMaxDynamicSharedMemorySize, SMEM_TOTAL);

    norm_kernel<<<BROWS / 8, 256>>>(zi, zj);
    gemm_kernel<<<TOTAL_TILES, 128, SMEM_TOTAL>>>();
    finish_kernel<<<1, 1>>>(out);
}

// round 5
// speedup vs baseline: 1.5556x; 1.0296x over previous
#include <cuda_runtime.h>
#include <cuda_fp16.h>
#include <cstdint>
#include <math.h>

// ---------------------------------------------------------------------------
// Problem constants
// ---------------------------------------------------------------------------
#define NROWS     8192     // rows in z_i (and z_j)
#define DIM       512      // feature dim
#define BROWS     16384    // combined B rows (zi ++ zj)

#define BM        128      // CTA tile M
#define BN        128      // CTA tile N
#define BK        64       // K chunk (fp16 elems) = 128 bytes/row
#define CHUNKS    (DIM / BK)   // 8
#define STAGES    3

#define CHUNK_A_BYTES (BM * BK * 2)          // 16384
#define CHUNK_B_BYTES (BN * BK * 2)          // 16384
#define STAGE_BYTES   (CHUNK_A_BYTES + CHUNK_B_BYTES)  // 32768
#define SMEM_TOTAL    (STAGES * STAGE_BYTES)           // 98304 -> 2 CTAs/SM

#define NEG_TILES 4096     // 64 x 64 full tiles for zi x zj
#define POS_TILES 2080     // upper triangle incl diag of 64x64 blocks (zi x zi)
#define TOTAL_TILES (NEG_TILES + POS_TILES)  // 6176

// ---------------------------------------------------------------------------
// Global scratch (allocation-free rules: __device__ globals)
// ---------------------------------------------------------------------------
__device__ __half g_z[(size_t)BROWS * DIM];   // 16 MB: rows 0..8191 zi, 8192.. zj
__device__ double g_pos;
__device__ double g_neg;

// ---------------------------------------------------------------------------
// PTX helpers — only sm_80-era features (PTX target is plain sm_103; no tcgen05)
// ---------------------------------------------------------------------------
__device__ __forceinline__ uint32_t smem_to_u32(const void* p) {
    uint32_t a;
    asm("{ .reg .u64 t; cvta.to.shared.u64 t, %1; cvt.u32.u64 %0, t; }" : "=r"(a) : "l"(p));
    return a;
}

#define SWZ(off) ((off) ^ (((off) >> 3) & 0x70u))   // SW128 swizzle for 128B rows

__device__ __forceinline__ void cp_async16(uint32_t dst_smem, const void* src) {
    asm volatile("cp.async.cg.shared.global [%0], [%1], 16;" :: "r"(dst_smem), "l"(src));
}
#define CP_ASYNC_COMMIT() asm volatile("cp.async.commit_group;" ::: "memory")
#define CP_ASYNC_WAIT_1() asm volatile("cp.async.wait_group 1;" ::: "memory")

__device__ __forceinline__ void ldmatrix_x4(uint32_t* r, uint32_t addr) {
    asm volatile("ldmatrix.sync.aligned.m8n8.x4.shared.b16 {%0,%1,%2,%3}, [%4];"
                 : "=r"(r[0]), "=r"(r[1]), "=r"(r[2]), "=r"(r[3]) : "r"(addr));
}

// D = A * B^T accumulate: mma.sync m16n8k16, fp16 in, fp16 accum (2 packed regs)
__device__ __forceinline__ void mma_f16(uint32_t* c, const uint32_t* a, uint32_t b0, uint32_t b1) {
    asm volatile(
        "mma.sync.aligned.m16n8k16.row.col.f16.f16.f16.f16 "
        "{%0,%1}, {%2,%3,%4,%5}, {%6,%7}, {%0,%1};"
        : "+r"(c[0]), "+r"(c[1])
        : "r"(a[0]), "r"(a[1]), "r"(a[2]), "r"(a[3]), "r"(b0), "r"(b1));
}

// ---------------------------------------------------------------------------
// Kernel 1: L2-normalize rows into fp16 g_z. One warp per row, 4 independent
// float4 loads per lane (MLP=4). Also resets accumulators.
// ---------------------------------------------------------------------------
__global__ __launch_bounds__(256) void norm_kernel(const float* __restrict__ zi,
                                                   const float* __restrict__ zj) {
    const int tid  = threadIdx.x;
    const int lane = tid & 31;
    const int row  = blockIdx.x * 8 + (tid >> 5);   // 2048 blocks x 8 warps
    if (blockIdx.x == 0 && tid == 0) { g_pos = 0.0; g_neg = 0.0; }

    const float* src = (row < NROWS) ? (zi + (size_t)row * DIM)
                                     : (zj + (size_t)(row - NROWS) * DIM);
    const float4* s4 = reinterpret_cast<const float4*>(src);
    float4 v[4];
    #pragma unroll
    for (int k = 0; k < 4; k++) v[k] = s4[lane + 32 * k];

    float ss = 0.0f;
    #pragma unroll
    for (int k = 0; k < 4; k++)
        ss += v[k].x * v[k].x + v[k].y * v[k].y + v[k].z * v[k].z + v[k].w * v[k].w;
    #pragma unroll
    for (int off = 16; off > 0; off >>= 1)
        ss += __shfl_xor_sync(0xFFFFFFFFu, ss, off);

    float scale = 1.0f / fmaxf(sqrtf(ss), 1e-12f);

    __half2* dst = reinterpret_cast<__half2*>(g_z + (size_t)row * DIM);
    #pragma unroll
    for (int k = 0; k < 4; k++) {
        int e = lane + 32 * k;
        dst[e * 2 + 0] = __floats2half2_rn(v[k].x * scale, v[k].y * scale);
        dst[e * 2 + 1] = __floats2half2_rn(v[k].z * scale, v[k].w * scale);
    }
}

// ---------------------------------------------------------------------------
// Kernel 2: fused GEMM (mma.sync fp16/fp16-accum) + weighted exp-sum epilogue.
// 128x128 tiles, 4 warps (64x64 warp tile), 2 CTAs/SM (96KB smem each).
// Tile decode (1-D grid, 6176 tiles):
//   idx < 4096 : neg tile: tm = idx&63, B rows = NROWS + (idx>>6)*128, w=1
//   idx >= 4096: pos tile p -> lower-tri (t,i), i<=t: tm=i, B rows = t*128,
//                w = (i==t) ? 1 : 2   (symmetry of zi x zi^T)
// ---------------------------------------------------------------------------
__global__ __launch_bounds__(128, 2) void gemm_kernel() {
    extern __shared__ __align__(1024) char smem[];
    const uint32_t sb = smem_to_u32(smem);
    const int tid   = threadIdx.x;
    const int wid   = tid >> 5;
    const int lane  = tid & 31;
    const int warpM = (wid & 1) * 64;
    const int warpN = (wid >> 1) * 64;

    // ---- tile decode ----
    int tm, rowB;
    float wtile;
    bool is_pos;
    {
        int idx = blockIdx.x;
        if (idx < NEG_TILES) {
            tm    = idx & 63;
            rowB  = NROWS + (idx >> 6) * BN;
            wtile = 1.0f;
            is_pos = false;
        } else {
            int p = idx - NEG_TILES;                    // 0 .. 2079
            int t = (int)((sqrtf((float)(8 * p + 1)) - 1.0f) * 0.5f);
            while ((t + 1) * (t + 2) / 2 <= p) t++;
            while (t * (t + 1) / 2 > p) t--;
            int i = p - t * (t + 1) / 2;                // 0 .. t
            tm    = i;
            rowB  = t * BN;
            wtile = (i == t) ? 1.0f : 2.0f;
            is_pos = true;
        }
    }

    const char* gzA = reinterpret_cast<const char*>(g_z) + (size_t)tm * BM * (DIM * 2);
    const char* gzB = reinterpret_cast<const char*>(g_z) + (size_t)rowB * (DIM * 2);

    uint32_t acc[4][8][2];    // fp16x2 accumulators: [mBlock16][nBlock8][pair] = 64 regs
    #pragma unroll
    for (int i = 0; i < 4; i++)
        #pragma unroll
        for (int j = 0; j < 8; j++) { acc[i][j][0] = 0u; acc[i][j][1] = 0u; }

    // -------- chunk loader: 16 x cp.async(16B) per thread (A 8 + B 8) --------
    auto load_chunk = [&](int c, int st) {
        uint32_t stA = sb + st * STAGE_BYTES;
        uint32_t stB = stA + CHUNK_A_BYTES;
        const char* srcA = gzA + c * (BK * 2);   // 128 bytes of K
        const char* srcB = gzB + c * (BK * 2);
        #pragma unroll
        for (int i = 0; i < 8; i++) {            // A: 1024 16B units / 128 thr
            int u = tid + i * 128;
            int r = u >> 3, c16 = u & 7;
            uint32_t off = (uint32_t)(r * 128 + c16 * 16);
            cp_async16(stA + SWZ(off), srcA + (size_t)r * (DIM * 2) + c16 * 16);
        }
        #pragma unroll
        for (int i = 0; i < 8; i++) {            // B: 1024 16B units / 128 thr
            int u = tid + i * 128;
            int r = u >> 3, c16 = u & 7;
            uint32_t off = (uint32_t)(r * 128 + c16 * 16);
            cp_async16(stB + SWZ(off), srcB + (size_t)r * (DIM * 2) + c16 * 16);
        }
        CP_ASYNC_COMMIT();
    };

    // -------- chunk compute: 4 ksteps x (8 ldmatrix.x4 + 32 mma) --------
    const int ldRow  = lane & 15;          // row within 16-row ldmatrix block
    const int ldColB = (lane >> 4) << 4;   // 0 or 16 bytes

    auto compute_chunk = [&](int st) {
        uint32_t stA = sb + st * STAGE_BYTES;
        uint32_t stB = stA + CHUNK_A_BYTES;
        #pragma unroll
        for (int ks = 0; ks < 4; ks++) {
            uint32_t a[4][4], b[4][4];
            #pragma unroll
            for (int mb = 0; mb < 4; mb++) {
                uint32_t off = (uint32_t)((warpM + mb * 16 + ldRow) * 128 + ks * 32 + ldColB);
                ldmatrix_x4(a[mb], stA + SWZ(off));
            }
            #pragma unroll
            for (int nb = 0; nb < 4; nb++) {
                uint32_t off = (uint32_t)((warpN + nb * 16 + ldRow) * 128 + ks * 32 + ldColB);
                ldmatrix_x4(b[nb], stB + SWZ(off));
            }
            #pragma unroll
            for (int mb = 0; mb < 4; mb++)
                #pragma unroll
                for (int nb = 0; nb < 4; nb++) {
                    mma_f16(acc[mb][nb * 2 + 0], a[mb], b[nb][0], b[nb][2]);
                    mma_f16(acc[mb][nb * 2 + 1], a[mb], b[nb][1], b[nb][3]);
                }
        }
    };

    // -------- 3-stage pipeline --------
    load_chunk(0, 0);
    load_chunk(1, 1);

    #pragma unroll 1
    for (int c = 0; c < CHUNKS; c++) {
        CP_ASYNC_WAIT_1();      // chunk c resident (<=1 group pending)
        __syncthreads();        // all threads' loads of chunk c visible; prev compute done
        int nc = c + 2;
        if (nc < CHUNKS) load_chunk(nc, nc % STAGES);  // slot held chunk c-1: free
        compute_chunk(c % STAGES);
    }

    // -------- epilogue: weighted sum of exp(10 * acc) --------
    float lsum = 0.0f;
    #pragma unroll
    for (int i = 0; i < 4; i++)
        #pragma unroll
        for (int j = 0; j < 8; j++)
            #pragma unroll
            for (int k = 0; k < 2; k++) {
                float2 f = __half22float2(*reinterpret_cast<const __half2*>(&acc[i][j][k]));
                lsum += __expf(10.0f * f.x) + __expf(10.0f * f.y);
            }
    lsum *= wtile;

    #pragma unroll
    for (int off = 16; off > 0; off >>= 1)
        lsum += __shfl_xor_sync(0xFFFFFFFFu, lsum, off);

    __shared__ double wsum[4];
    if (lane == 0) wsum[wid] = (double)lsum;
    __syncthreads();
    if (tid == 0) {
        double t = wsum[0] + wsum[1] + wsum[2] + wsum[3];
        atomicAdd(is_pos ? &g_pos : &g_neg, t);
    }
}

// ---------------------------------------------------------------------------
// Kernel 3: loss = -log(pos / (neg + pos))
// ---------------------------------------------------------------------------
__global__ void finish_kernel(float* out) {
    double p = g_pos, n = g_neg;
    out[0] = (float)(-log(p / (n + p)));
}

// ---------------------------------------------------------------------------
extern "C" void kernel_launch(void* const* d_in, const int* in_sizes, int n_in,
                              void* d_out, int out_size) {
    const float* zi = (const float*)d_in[0];
    const float* zj = (const float*)d_in[1];
    float* out = (float*)d_out;

    cudaFuncSetAttribute(gemm_kernel, cudaFuncAttributeMaxDynamicSharedMemorySize, SMEM_TOTAL);

    norm_kernel<<<BROWS / 8, 256>>>(zi, zj);
    gemm_kernel<<<TOTAL_TILES, 128, SMEM_TOTAL>>>();
    finish_kernel<<<1, 1>>>(out);
}